// round 7
// baseline (speedup 1.0000x reference)
#include <cuda_runtime.h>
#include <math.h>

#define SS 512
#define CC 384
#define HH 12
#define NPROJ 1152   // 192 qs + 192 ks + 192 vs + 144 qp + 144 kp + 288 vp
#define AD 32        // augmented logit dim (30 used, padded to 32)
#define VD 40        // 16 scalar + 8 points * 3
#define COMB 576     // 192 scalar_out + 288 pol + 96 norms
#define LGS 516      // padded lg row stride (516 % 32 = 4 -> no bank conflict)

// ---------------- scratch (device globals; no allocation allowed) ----------
__device__ float g_Wc[CC * NPROJ];
__device__ float g_bc[NPROJ];
__device__ float g_proj[SS * NPROJ];
__device__ float g_Qa[HH * AD * SS];     // dim-major augmented Q
__device__ float g_Ka[HH * AD * SS];     // dim-major augmented K
__device__ float g_Vc[HH * SS * VD];
__device__ float g_out40[HH * SS * VD];
__device__ float g_comb[SS * COMB];
__device__ float g_maskf[SS];
__device__ float g_spw[HH * 4];          // softplus(point_weights)

// ---------------- K0: pack weights (float4 segment copies) + mask + softplus
__global__ void pack_weights(const float* __restrict__ Wq_s, const float* __restrict__ Wk_s,
                             const float* __restrict__ Wv_s, const float* __restrict__ Wq_p,
                             const float* __restrict__ Wk_p, const float* __restrict__ Wv_p,
                             const float* __restrict__ bq_s, const float* __restrict__ bk_s,
                             const float* __restrict__ bv_s, const float* __restrict__ bq_p,
                             const float* __restrict__ bk_p, const float* __restrict__ bv_p,
                             const float* __restrict__ pw,
                             const unsigned char* __restrict__ msk) {
    if (blockIdx.x == 0) {
        __shared__ int flag;
        int t = threadIdx.x;             // 256
        if (t == 0) flag = 0;
        __syncthreads();
        #pragma unroll
        for (int b = t; b < 512; b += 256)
            if ((b & 3) != 0 && msk[b] != 0) atomicOr(&flag, 1);
        __syncthreads();
        for (int i = t; i < SS; i += 256)
            g_maskf[i] = flag ? (msk[i] != 0 ? 1.0f : 0.0f)
                              : (((const int*)msk)[i] != 0 ? 1.0f : 0.0f);
        if (t < HH * 4) {
            float x = pw[t];
            g_spw[t] = (x > 20.0f) ? x : log1pf(expf(x));
        }
    }
    const int ROW4 = NPROJ / 4;          // 288
    const int TOT4 = CC * ROW4;          // 110592
    float4* dstW = (float4*)g_Wc;
    for (int idx = blockIdx.x * blockDim.x + threadIdx.x; idx < TOT4 + ROW4;
         idx += gridDim.x * blockDim.x) {
        if (idx < TOT4) {
            int row = idx / ROW4, r = idx % ROW4;
            const float* src;  int c4, w4;
            if      (r < 48)  { src = Wq_s; c4 = r;        w4 = 48; }
            else if (r < 96)  { src = Wk_s; c4 = r - 48;   w4 = 48; }
            else if (r < 144) { src = Wv_s; c4 = r - 96;   w4 = 48; }
            else if (r < 180) { src = Wq_p; c4 = r - 144;  w4 = 36; }
            else if (r < 216) { src = Wk_p; c4 = r - 180;  w4 = 36; }
            else              { src = Wv_p; c4 = r - 216;  w4 = 72; }
            dstW[idx] = ((const float4*)src)[row * w4 + c4];
        } else {
            int r = idx - TOT4;
            const float* src;  int c4;
            if      (r < 48)  { src = bq_s; c4 = r; }
            else if (r < 96)  { src = bk_s; c4 = r - 48; }
            else if (r < 144) { src = bv_s; c4 = r - 96; }
            else if (r < 180) { src = bq_p; c4 = r - 144; }
            else if (r < 216) { src = bk_p; c4 = r - 180; }
            else              { src = bv_p; c4 = r - 216; }
            ((float4*)g_bc)[r] = ((const float4*)src)[c4];
        }
    }
}

// ---------------- generic SGEMM (double-buffered): C = A@W + bias, row mask
__global__ void gemm64(const float* __restrict__ A, const float* __restrict__ W,
                       const float* __restrict__ bias, float* __restrict__ Cmat,
                       int M, int N, int K, const float* __restrict__ mask) {
    __shared__ __align__(16) float As[2][16][64];
    __shared__ __align__(16) float Ws[2][16][64];
    int tid = threadIdx.x;
    int tx = tid & 15, ty = tid >> 4;
    int n0 = blockIdx.x * 64, m0 = blockIdx.y * 64;

    int kkA[4], mA[4], nW[4], kkW[4];
    #pragma unroll
    for (int l = 0; l < 4; ++l) {
        int e = tid + l * 256;
        kkA[l] = e & 15;  mA[l] = e >> 4;
        nW[l]  = e & 63;  kkW[l] = e >> 6;
    }
    #pragma unroll
    for (int l = 0; l < 4; ++l) {
        As[0][kkA[l]][mA[l]] = A[(m0 + mA[l]) * K + kkA[l]];
        Ws[0][kkW[l]][nW[l]] = W[kkW[l] * N + n0 + nW[l]];
    }
    __syncthreads();

    float acc[4][4] = {};
    int nt = K >> 4;
    for (int t = 0; t < nt; ++t) {
        int cur = t & 1;
        float ar[4], wr[4];
        if (t + 1 < nt) {
            int k0n = (t + 1) << 4;
            #pragma unroll
            for (int l = 0; l < 4; ++l) {
                ar[l] = A[(m0 + mA[l]) * K + k0n + kkA[l]];
                wr[l] = W[(k0n + kkW[l]) * N + n0 + nW[l]];
            }
        }
        #pragma unroll
        for (int kk = 0; kk < 16; ++kk) {
            float4 a4 = *(const float4*)&As[cur][kk][ty * 4];
            float4 b4 = *(const float4*)&Ws[cur][kk][tx * 4];
            float av[4] = {a4.x, a4.y, a4.z, a4.w};
            float bv[4] = {b4.x, b4.y, b4.z, b4.w};
            #pragma unroll
            for (int i = 0; i < 4; ++i)
                #pragma unroll
                for (int j = 0; j < 4; ++j) acc[i][j] += av[i] * bv[j];
        }
        if (t + 1 < nt) {
            #pragma unroll
            for (int l = 0; l < 4; ++l) {
                As[cur ^ 1][kkA[l]][mA[l]] = ar[l];
                Ws[cur ^ 1][kkW[l]][nW[l]] = wr[l];
            }
        }
        __syncthreads();
    }
    #pragma unroll
    for (int i = 0; i < 4; ++i) {
        int m = m0 + ty * 4 + i;
        float sc = mask ? mask[m] : 1.0f;
        #pragma unroll
        for (int j = 0; j < 4; ++j) {
            int n = n0 + tx * 4 + j;
            Cmat[m * N + n] = (acc[i][j] + bias[n]) * sc;
        }
    }
}

// ---------------- K2: rotate points, build augmented Q̃/K̃ (dim-major) + V --
__global__ void rotate_pack(const float* __restrict__ rot, const float* __restrict__ trans) {
    int s = blockIdx.x;
    int t = threadIdx.x;                 // 128 threads
    __shared__ float pts[576];
    __shared__ float Rs[9], ts_[3];
    if (t < 9) Rs[t] = rot[s * 9 + t];
    if (t >= 16 && t < 19) ts_[t - 16] = trans[s * 3 + (t - 16)];
    const float* pr = g_proj + s * NPROJ;

    #pragma unroll
    for (int e = t; e < 576; e += 128) {
        float v = pr[e];
        int seg = e / 192, r = e % 192;
        int h = r >> 4, d = r & 15;
        if      (seg == 0) g_Qa[h * (AD * SS) + d * SS + s] = 0.25f * v;
        else if (seg == 1) g_Ka[h * (AD * SS) + d * SS + s] = v;
        else               g_Vc[(h * SS + s) * VD + d] = v;
    }
    #pragma unroll
    for (int e = t; e < 576; e += 128) pts[e] = pr[576 + e];
    __syncthreads();

    if (t < 24) {
        bool isQ = t < 12;
        int h = isQ ? t : t - 12;
        const float* p = pts + (isQ ? 0 : 144) + h * 12;
        float* base = (isQ ? g_Qa : g_Ka) + h * (AD * SS);
        float s2 = 0.0f;
        #pragma unroll
        for (int pp = 0; pp < 4; ++pp) {
            float x = p[pp * 3 + 0], y = p[pp * 3 + 1], z = p[pp * 3 + 2];
            float gx = Rs[0] * x + Rs[1] * y + Rs[2] * z + ts_[0];
            float gy = Rs[3] * x + Rs[4] * y + Rs[5] * z + ts_[1];
            float gz = Rs[6] * x + Rs[7] * y + Rs[8] * z + ts_[2];
            float w = g_spw[h * 4 + pp];
            s2 += w * (gx * gx + gy * gy + gz * gz);
            float m = isQ ? w : 1.0f;
            base[(16 + pp * 3 + 0) * SS + s] = m * gx;
            base[(16 + pp * 3 + 1) * SS + s] = m * gy;
            base[(16 + pp * 3 + 2) * SS + s] = m * gz;
        }
        base[28 * SS + s] = isQ ? -0.5f * s2 : 1.0f;
        base[29 * SS + s] = isQ ? 1.0f : -0.5f * s2;
        base[30 * SS + s] = 0.0f;
        base[31 * SS + s] = 0.0f;
    } else if (t >= 32) {
        int q = t - 32;                   // 96 v-point tasks
        const float* p = pts + 288 + q * 3;
        float* o = g_Vc + ((q >> 3) * SS + s) * VD + 16 + (q & 7) * 3;
        float x = p[0], y = p[1], z = p[2];
        o[0] = Rs[0] * x + Rs[1] * y + Rs[2] * z + ts_[0];
        o[1] = Rs[3] * x + Rs[4] * y + Rs[5] * z + ts_[1];
        o[2] = Rs[6] * x + Rs[7] * y + Rs[8] * z + ts_[2];
    }
}

// ---------------- K3: fused logits + softmax + attn@V ----------------------
// Block = (32 queries, head). Dynamic smem: lg[32][LGS] | Qs[32][32] |
// Ks[32][128] | vv[64][VD].  96768 bytes total.
__global__ void fused_attn() {
    extern __shared__ __align__(16) float sm[];
    float* lg = sm;                          // 32*LGS = 16512
    float* Qs = lg + 32 * LGS;               // 32*32  = 1024  (Qs[d][q])
    float* Ks = Qs + 1024;                   // 32*128 = 4096  (Ks[d][k])
    float* vv = Ks + 4096;                   // 64*VD  = 2560

    int h = blockIdx.y;
    int i0 = blockIdx.x * 32;
    int tid = threadIdx.x;                   // 256
    const float* qb = g_Qa + h * (AD * SS);
    const float* kb = g_Ka + h * (AD * SS);

    // load Q block: Qs[d][q] (coalesced along q)
    #pragma unroll
    for (int l = 0; l < 4; ++l) {
        int idx = tid + l * 256;
        int d = idx >> 5, q = idx & 31;
        Qs[d * 32 + q] = qb[d * SS + i0 + q];
    }

    // ---- phase 1: logits into lg, 4 chunks of 128 keys ----
    int tx = tid & 31, ty = tid >> 5;        // tx: key-group, ty: query-group
    for (int c = 0; c < 4; ++c) {
        int j0 = c * 128;
        #pragma unroll
        for (int l = 0; l < 4; ++l) {
            int idx = tid + l * 256;         // 1024 float4 slots
            int d = idx >> 5, n4 = idx & 31;
            *(float4*)&Ks[d * 128 + n4 * 4] = *(const float4*)&kb[d * SS + j0 + n4 * 4];
        }
        __syncthreads();
        float acc[4][4] = {};
        #pragma unroll
        for (int d = 0; d < AD; ++d) {
            float4 k4 = *(const float4*)&Ks[d * 128 + tx * 4];
            float4 q4 = *(const float4*)&Qs[d * 32 + ty * 4];
            float av[4] = {q4.x, q4.y, q4.z, q4.w};
            float bv[4] = {k4.x, k4.y, k4.z, k4.w};
            #pragma unroll
            for (int i = 0; i < 4; ++i)
                #pragma unroll
                for (int j = 0; j < 4; ++j) acc[i][j] += av[i] * bv[j];
        }
        float4 mq = ((const float4*)g_maskf)[(j0 >> 2) + tx];
        #pragma unroll
        for (int i = 0; i < 4; ++i) {
            float4 v;
            v.x = (mq.x != 0.0f) ? acc[i][0] : -10000.0f;
            v.y = (mq.y != 0.0f) ? acc[i][1] : -10000.0f;
            v.z = (mq.z != 0.0f) ? acc[i][2] : -10000.0f;
            v.w = (mq.w != 0.0f) ? acc[i][3] : -10000.0f;
            *(float4*)&lg[(ty * 4 + i) * LGS + j0 + tx * 4] = v;
        }
        __syncthreads();
    }

    // ---- phase 2: softmax (8 warps x 4 rows each) ----
    int lane = tid & 31;
    #pragma unroll
    for (int rr = 0; rr < 4; ++rr) {
        int row = ty + rr * 8;
        float* r = lg + row * LGS;
        float m = -1e30f;
        #pragma unroll
        for (int c = 0; c < 16; ++c) m = fmaxf(m, r[lane + c * 32]);
        #pragma unroll
        for (int o = 16; o; o >>= 1) m = fmaxf(m, __shfl_xor_sync(0xFFFFFFFFu, m, o));
        float sum = 0.0f;
        #pragma unroll
        for (int c = 0; c < 16; ++c) {
            float e = __expf(r[lane + c * 32] - m);
            r[lane + c * 32] = e;
            sum += e;
        }
        #pragma unroll
        for (int o = 16; o; o >>= 1) sum += __shfl_xor_sync(0xFFFFFFFFu, sum, o);
        float inv = g_maskf[i0 + row] / sum;
        #pragma unroll
        for (int c = 0; c < 16; ++c) r[lane + c * 32] *= inv;
    }
    __syncthreads();

    // ---- phase 3: attn @ V, 8 chunks of 64 keys ----
    int il = tid >> 3, dg = tid & 7;         // 32 queries x 8 dim-groups (5 dims)
    float acc[5] = {};
    for (int j0 = 0; j0 < SS; j0 += 64) {
        #pragma unroll
        for (int l = 0; l < 3; ++l) {
            int idx = tid + l * 256;
            if (idx < 640) {
                int rr = idx / 10, c4 = idx % 10;
                *(float4*)&vv[rr * VD + c4 * 4] =
                    ((const float4*)(g_Vc + (h * SS + j0 + rr) * VD))[c4];
            }
        }
        __syncthreads();
        const float* lrow = lg + il * LGS + j0;
        #pragma unroll 8
        for (int jj = 0; jj < 64; ++jj) {
            float a = lrow[jj];
            #pragma unroll
            for (int q = 0; q < 5; ++q) acc[q] += a * vv[jj * VD + dg * 5 + q];
        }
        __syncthreads();
    }
    #pragma unroll
    for (int q = 0; q < 5; ++q)
        g_out40[(h * SS + i0 + il) * VD + dg * 5 + q] = acc[q];
}

// ---------------- K5: build combined = [scalar_out | pol | point_norm] -----
__global__ void build_combined(const float* __restrict__ rot, const float* __restrict__ trans) {
    const int NSC = SS * 192;
    const int NPT = SS * 96;
    int idx = blockIdx.x * blockDim.x + threadIdx.x;
    if (idx < NSC) {
        int s = idx / 192, c = idx % 192;
        int h = c >> 4, d = c & 15;
        g_comb[s * COMB + c] = g_out40[(h * SS + s) * VD + d];
    } else if (idx < NSC + NPT) {
        int r = idx - NSC;
        int s = r / 96, q = r % 96;
        int h = q >> 3, p = q & 7;
        const float* o = g_out40 + (h * SS + s) * VD + 16 + 3 * p;
        float v0 = o[0] - trans[s * 3 + 0];
        float v1 = o[1] - trans[s * 3 + 1];
        float v2 = o[2] - trans[s * 3 + 2];
        const float* R = rot + s * 9;
        float p0 = R[0] * v0 + R[3] * v1 + R[6] * v2;
        float p1 = R[1] * v0 + R[4] * v1 + R[7] * v2;
        float p2 = R[2] * v0 + R[5] * v1 + R[8] * v2;
        float* cb = g_comb + s * COMB;
        cb[192 + (h * 8 + p) * 3 + 0] = p0;
        cb[192 + (h * 8 + p) * 3 + 1] = p1;
        cb[192 + (h * 8 + p) * 3 + 2] = p2;
        cb[480 + h * 8 + p] = sqrtf(p0 * p0 + p1 * p1 + p2 * p2);
    }
}

// ---------------------------------------------------------------------------
extern "C" void kernel_launch(void* const* d_in, const int* in_sizes, int n_in,
                              void* d_out, int out_size) {
    const float* single = (const float*)d_in[0];
    const float* rot    = (const float*)d_in[1];
    const float* trans  = (const float*)d_in[2];
    const float* Wq_s = (const float*)d_in[3];  const float* bq_s = (const float*)d_in[4];
    const float* Wk_s = (const float*)d_in[5];  const float* bk_s = (const float*)d_in[6];
    const float* Wv_s = (const float*)d_in[7];  const float* bv_s = (const float*)d_in[8];
    const float* Wq_p = (const float*)d_in[9];  const float* bq_p = (const float*)d_in[10];
    const float* Wk_p = (const float*)d_in[11]; const float* bk_p = (const float*)d_in[12];
    const float* Wv_p = (const float*)d_in[13]; const float* bv_p = (const float*)d_in[14];
    const float* pw   = (const float*)d_in[15];
    const float* Wo   = (const float*)d_in[16];
    const float* bo   = (const float*)d_in[17];
    const unsigned char* mask = (const unsigned char*)d_in[18];
    float* out = (float*)d_out;

    float *pWc, *pbc, *pproj, *pcomb, *pmaskf;
    cudaGetSymbolAddress((void**)&pWc,    g_Wc);
    cudaGetSymbolAddress((void**)&pbc,    g_bc);
    cudaGetSymbolAddress((void**)&pproj,  g_proj);
    cudaGetSymbolAddress((void**)&pcomb,  g_comb);
    cudaGetSymbolAddress((void**)&pmaskf, g_maskf);

    const int FUSED_SMEM = (32 * LGS + 32 * 32 + 32 * 128 + 64 * VD) * 4;
    cudaFuncSetAttribute(fused_attn, cudaFuncAttributeMaxDynamicSharedMemorySize,
                         FUSED_SMEM);

    pack_weights<<<432, 256>>>(Wq_s, Wk_s, Wv_s, Wq_p, Wk_p, Wv_p,
                               bq_s, bk_s, bv_s, bq_p, bk_p, bv_p, pw, mask);
    gemm64<<<dim3(NPROJ / 64, SS / 64), 256>>>(single, pWc, pbc, pproj,
                                               SS, NPROJ, CC, (const float*)0);
    rotate_pack<<<SS, 128>>>(rot, trans);
    fused_attn<<<dim3(SS / 32, HH), 256, FUSED_SMEM>>>();
    build_combined<<<(SS * 192 + SS * 96 + 255) / 256, 256>>>(rot, trans);
    gemm64<<<dim3(CC / 64, SS / 64), 256>>>(pcomb, Wo, bo, out, SS, CC, COMB, pmaskf);
}